// round 9
// baseline (speedup 1.0000x reference)
#include <cuda_runtime.h>
#include <cstdint>
#include <cstddef>

#define D 128
#define NVEC 65536                 // 16 * 64 * 64
#define OUT_TENSOR 67108864LL      // 8*16*128*64*64

// -------- scratch (static device globals; no runtime allocation) --------
__device__ uint8_t g_idxb[8 * NVEC];   // level-major byte indices
__device__ float   g_part[256 * 8];    // per-CTA loss partials

// stage -> SLOT indices into the packed 10 distinct rows (c_rl order)
__constant__ int c_st[16]   = {0,1, 2,3, 3,4, 4,5, 5,6, 6,7, 7,8, 8,9};
__constant__ int c_rl[10]   = {0, 1, 3, 4, 5, 6, 7, 8, 9, 10};   // distinct rows
__constant__ int c_pad[8]   = {0, 4, 8, 16, 48, 112, 240, 496};
__constant__ float c_coef[8] = {1.5f, 1.2f, 1.0f, 0.9f, 0.82f, 0.69f, 0.65f, 0.56f};
// upper-triangular pair list for the 10x10 gram matrix (slot indices)
__constant__ unsigned char c_pi[55] = {0,0,0,0,0,0,0,0,0,0, 1,1,1,1,1,1,1,1,1,
                                       2,2,2,2,2,2,2,2, 3,3,3,3,3,3,3, 4,4,4,4,4,4,
                                       5,5,5,5,5, 6,6,6,6, 7,7,7, 8,8, 9};
__constant__ unsigned char c_pj[55] = {0,1,2,3,4,5,6,7,8,9, 1,2,3,4,5,6,7,8,9,
                                       2,3,4,5,6,7,8,9, 3,4,5,6,7,8,9, 4,5,6,7,8,9,
                                       5,6,7,8,9, 6,7,8,9, 7,8,9, 8,9, 9};

__device__ __forceinline__ void ffma2(unsigned long long& d,
                                      unsigned long long a, unsigned long long b) {
    asm("fma.rn.f32x2 %0, %1, %2, %0;" : "+l"(d) : "l"(a), "l"(b));
}
__device__ __forceinline__ void unpack2(unsigned long long v, float& lo, float& hi) {
    asm("mov.b64 {%0, %1}, %2;" : "=f"(lo), "=f"(hi) : "l"(v));
}

// ---------------------------------------------------------------------------
// Kernel 1: per-vector quantization. Self-contained: 10x10 Gram + all 510
// codeword norms computed in the CTA prelude with ALL lookup tables in smem
// (the R5 slowness was divergent indexed-constant LDC, fixed here).
// ---------------------------------------------------------------------------
__global__ void __launch_bounds__(256, 2)
quant_kernel(const float* __restrict__ inp, const float* __restrict__ w) {
    __shared__ __align__(16) float s_bvp[128][12];   // per channel: 10 slots *(-2), pad 2
    __shared__ float sG[100];                        // gram of scaled rows (= 4 * true gram)
    __shared__ float sC[768];                        // padded codeword norms
    __shared__ float s_loss[8];
    __shared__ int   sst[16];
    __shared__ int   spad[8];

    int tid = threadIdx.x, wid = tid >> 5, lane = tid & 31;

    if (tid < 16) sst[tid] = c_st[tid];
    if (tid >= 16 && tid < 24) spad[tid - 16] = c_pad[tid - 16];
    for (int i = tid; i < 1280; i += 256) {
        int c = i & 127, t = i >> 7;
        s_bvp[c][t] = -2.0f * w[c_rl[t] * D + c];
    }
    { int c = tid & 127, t = tid >> 7; s_bvp[c][10 + t] = 0.f; }
    if (tid < 8) s_loss[tid] = 0.f;
    __syncthreads();

    // gram over SLOTS (55 pairs across 8 warps)
    for (int p = wid; p < 55; p += 8) {
        int i = c_pi[p], j = c_pj[p];
        float s = 0.f;
        #pragma unroll
        for (int cc = 0; cc < 4; cc++)
            s = fmaf(s_bvp[lane + 32 * cc][i], s_bvp[lane + 32 * cc][j], s);
        #pragma unroll
        for (int o = 16; o; o >>= 1) s += __shfl_xor_sync(0xffffffffu, s, o);
        if (lane == 0) { sG[i * 10 + j] = s; sG[j * 10 + i] = s; }
    }
    __syncthreads();

    // codeword norms: ||sum rows||^2 = sum_{s,t} G[slot_s][slot_t]; gram scaled by 4
    for (int k = tid; k < 510; k += 256) {
        int li = 30 - __clz(k + 2);
        int L = li + 1, sz = 1 << L, j = k - (sz - 2);
        float n = 0.f;
        for (int s = 0; s < L; s++) {
            int ts = sst[2 * s + ((j >> (L - 1 - s)) & 1)];
            for (int t = 0; t < L; t++) {
                int tt = sst[2 * t + ((j >> (L - 1 - t)) & 1)];
                n += sG[ts * 10 + tt];
            }
        }
        sC[spad[li] + j] = 0.25f * n;
    }
    __syncthreads();

    int vec = blockIdx.x * 256 + tid;                     // 0..65535
    const float* xp = inp + ((size_t)(vec >> 12) << 19) + (vec & 4095);

    unsigned long long a01 = 0, a34 = 0, a56 = 0, a78 = 0, a910 = 0;
    float xn = 0.f;

    #pragma unroll 8
    for (int c = 0; c < 128; c++) {
        float x = xp[c * 4096];
        unsigned long long xx;
        asm("mov.b64 %0, {%1, %1};" : "=l"(xx) : "f"(x));
        const ulonglong2* bp = reinterpret_cast<const ulonglong2*>(&s_bvp[c][0]);
        ulonglong2 P0 = bp[0];
        ulonglong2 P1 = bp[1];
        unsigned long long P2 = reinterpret_cast<const unsigned long long*>(&s_bvp[c][0])[4];
        ffma2(a01,  xx, P0.x);
        ffma2(a34,  xx, P0.y);
        ffma2(a56,  xx, P1.x);
        ffma2(a78,  xx, P1.y);
        ffma2(a910, xx, P2);
        xn = fmaf(x, x, xn);
    }

    float d0, d1, d3, d4, d5, d6, d7, d8, d9, d10;
    unpack2(a01,  d0, d1);
    unpack2(a34,  d3, d4);
    unpack2(a56,  d5, d6);
    unpack2(a78,  d7, d8);
    unpack2(a910, d9, d10);

    // p[2s+b] = -2 x . v_{s,b}
    float p[16] = {d0, d1, d3, d4, d4, d5, d5, d6, d6, d7, d7, d8, d8, d9, d9, d10};

    float A2[4], A3[8], A4[16], B2[4], B3[8], B4[16];
    #pragma unroll
    for (int j = 0; j < 4;  j++) A2[j] = p[j >> 1] + p[2 + (j & 1)];
    #pragma unroll
    for (int j = 0; j < 8;  j++) A3[j] = A2[j >> 1] + p[4 + (j & 1)];
    #pragma unroll
    for (int j = 0; j < 16; j++) A4[j] = A3[j >> 1] + p[6 + (j & 1)];
    #pragma unroll
    for (int j = 0; j < 4;  j++) B2[j] = p[8 + (j >> 1)] + p[10 + (j & 1)];
    #pragma unroll
    for (int j = 0; j < 8;  j++) B3[j] = B2[j >> 1] + p[12 + (j & 1)];
    #pragma unroll
    for (int j = 0; j < 16; j++) B4[j] = B3[j >> 1] + p[14 + (j & 1)];

    const float INF = __int_as_float(0x7f800000);
    float m[8]; int mi[8];
    #pragma unroll
    for (int l = 0; l < 8; l++) { m[l] = INF; mi[l] = 0; }

    // strict '<' keeps the FIRST minimum (matches jnp.argmin tie-break)
    #pragma unroll
    for (int j = 0; j < 2;   j++) { float s = p[j]            + sC[0   + j]; if (s < m[0]) { m[0] = s; mi[0] = j; } }
    #pragma unroll
    for (int j = 0; j < 4;   j++) { float s = A2[j]           + sC[4   + j]; if (s < m[1]) { m[1] = s; mi[1] = j; } }
    #pragma unroll
    for (int j = 0; j < 8;   j++) { float s = A3[j]           + sC[8   + j]; if (s < m[2]) { m[2] = s; mi[2] = j; } }
    #pragma unroll
    for (int j = 0; j < 16;  j++) { float s = A4[j]           + sC[16  + j]; if (s < m[3]) { m[3] = s; mi[3] = j; } }
    #pragma unroll
    for (int j = 0; j < 32;  j++) { float s = A4[j >> 1] + p[8 + (j & 1)]  + sC[48  + j]; if (s < m[4]) { m[4] = s; mi[4] = j; } }
    #pragma unroll
    for (int j = 0; j < 64;  j++) { float s = A4[j >> 2] + B2[j & 3]       + sC[112 + j]; if (s < m[5]) { m[5] = s; mi[5] = j; } }
    #pragma unroll
    for (int j = 0; j < 128; j++) { float s = A4[j >> 3] + B3[j & 7]       + sC[240 + j]; if (s < m[6]) { m[6] = s; mi[6] = j; } }
    #pragma unroll
    for (int j = 0; j < 256; j++) { float s = A4[j >> 4] + B4[j & 15]      + sC[496 + j]; if (s < m[7]) { m[7] = s; mi[7] = j; } }

    // level-major byte indices (coalesced per level)
    #pragma unroll
    for (int l = 0; l < 8; l++) g_idxb[(l << 16) + vec] = (uint8_t)mi[l];

    #pragma unroll
    for (int l = 0; l < 8; l++) {
        float v = xn + m[l];
        #pragma unroll
        for (int o = 16; o; o >>= 1) v += __shfl_xor_sync(0xffffffffu, v, o);
        if (lane == 0) atomicAdd(&s_loss[l], v);
    }
    __syncthreads();
    if (tid < 8) g_part[blockIdx.x * 8 + tid] = s_loss[tid];
}

// ---------------------------------------------------------------------------
// Kernel 2: output writer. 256 CTAs = (8 levels x 16 batches x 2 channel-
// halves), 256 thr, ~71 KB static smem -> 2 CTAs/SM and grid <= resident:
// exactly one balanced wave (every CTA writes 1 MB). In-CTA codebook build
// for its 64 channels, channel-major scalar gather, STG.128 writes.
// ---------------------------------------------------------------------------
__global__ void __launch_bounds__(256, 2)
scatter_kernel(const float* __restrict__ w, float* __restrict__ out) {
    __shared__ float    scb[16384];    // 64 channels x sz (<=256) = 64 KB
    __shared__ float    srow[640];     // 10 slots x 64 channels
    __shared__ uint32_t sidx[1024];    // 4096 byte-indices
    __shared__ int      sst[16];

    int bid   = blockIdx.x;
    int level = bid >> 5;              // 0..7
    int r     = bid & 31;
    int b     = r >> 1;                // 0..15
    int h     = r & 1;                 // channel half (64 channels)
    int L     = level + 1;
    int sz    = 2 << level;
    int tid   = threadIdx.x;

    if (tid < 16) sst[tid] = c_st[tid];
    for (int i = tid; i < 640; i += 256)
        srow[i] = w[c_rl[i >> 6] * D + h * 64 + (i & 63)];
    {
        const uint4* src = reinterpret_cast<const uint4*>(
            g_idxb + ((size_t)level << 16) + ((size_t)b << 12));
        reinterpret_cast<uint4*>(sidx)[tid] = src[tid];
    }
    __syncthreads();

    // build codebook slice: scb[cl*sz + j], cl = local channel 0..63
    int n = sz << 6;
    for (int u = tid; u < n; u += 256) {
        int cl = u >> L;
        int j  = u & (sz - 1);
        float v = 0.f;
        #pragma unroll 8
        for (int s = 0; s < L; s++) {
            int bit = (j >> (L - 1 - s)) & 1;
            v += srow[sst[2 * s + bit] * 64 + cl];
        }
        scb[u] = v;
    }
    __syncthreads();

    // loss finalize (one CTA; quant complete by stream order)
    if (bid == 0) {
        int l = tid >> 5, ln = tid & 31;
        float s = 0.f;
        #pragma unroll
        for (int k = 0; k < 8; k++) s += g_part[(ln + 32 * k) * 8 + l];
        #pragma unroll
        for (int o = 16; o; o >>= 1) s += __shfl_xor_sync(0xffffffffu, s, o);
        if (ln == 0)
            out[OUT_TENSOR + l] = (c_coef[l] + 0.4f) * s * (1.0f / 8388608.0f);
    }

    // per-thread indices: quad g covers hw = g*1024 + 4*tid .. +3
    int o[16];
    #pragma unroll
    for (int g = 0; g < 4; g++) {
        uint32_t u = sidx[g * 256 + tid];
        o[4 * g + 0] =  u        & 255;
        o[4 * g + 1] = (u >> 8)  & 255;
        o[4 * g + 2] = (u >> 16) & 255;
        o[4 * g + 3] =  u >> 24;
    }

    // out index = ((level*16 + b)*128 + h*64 + cl) * 4096 + hw
    float* ob = out + ((((size_t)((level << 4) + b) << 7) + ((size_t)(h << 6))) << 12)
                    + (tid << 2);
    const float* row = scb;
    for (int cl = 0; cl < 64; cl++) {
        #pragma unroll
        for (int g = 0; g < 4; g++) {
            float4 v = make_float4(row[o[4 * g + 0]], row[o[4 * g + 1]],
                                   row[o[4 * g + 2]], row[o[4 * g + 3]]);
            *reinterpret_cast<float4*>(ob + g * 1024) = v;
        }
        row += sz;
        ob  += 4096;
    }
}

// ---------------------------------------------------------------------------
extern "C" void kernel_launch(void* const* d_in, const int* in_sizes, int n_in,
                              void* d_out, int out_size) {
    const float* inp = (const float*)d_in[0];   // (16,128,64,64) f32
    const float* w   = (const float*)d_in[1];   // (256,128) f32
    float* out       = (float*)d_out;

    (void)in_sizes; (void)n_in; (void)out_size;

    quant_kernel<<<256, 256>>>(inp, w);
    scatter_kernel<<<256, 256>>>(w, out);
}

// round 11
// speedup vs baseline: 1.1382x; 1.1382x over previous
#include <cuda_runtime.h>
#include <cstdint>
#include <cstddef>

#define D 128
#define NVEC 65536                 // 16 * 64 * 64
#define OUT_TENSOR 67108864LL      // 8*16*128*64*64

// -------- scratch (static device globals; no runtime allocation) --------
__device__ uint8_t g_idxb[8 * NVEC];   // level-major byte indices
__device__ float   g_part[128 * 8];    // per-CTA loss partials

// stage -> SLOT indices into the packed 10 distinct rows (c_rl order)
__constant__ int c_st[16]   = {0,1, 2,3, 3,4, 4,5, 5,6, 6,7, 7,8, 8,9};
__constant__ int c_rl[10]   = {0, 1, 3, 4, 5, 6, 7, 8, 9, 10};   // distinct rows
__constant__ float c_coef[8] = {1.5f, 1.2f, 1.0f, 0.9f, 0.82f, 0.69f, 0.65f, 0.56f};
// upper-triangular pair list for the 10x10 gram matrix (slot indices)
__constant__ unsigned char c_pi[55] = {0,0,0,0,0,0,0,0,0,0, 1,1,1,1,1,1,1,1,1,
                                       2,2,2,2,2,2,2,2, 3,3,3,3,3,3,3, 4,4,4,4,4,4,
                                       5,5,5,5,5, 6,6,6,6, 7,7,7, 8,8, 9};
__constant__ unsigned char c_pj[55] = {0,1,2,3,4,5,6,7,8,9, 1,2,3,4,5,6,7,8,9,
                                       2,3,4,5,6,7,8,9, 3,4,5,6,7,8,9, 4,5,6,7,8,9,
                                       5,6,7,8,9, 6,7,8,9, 7,8,9, 8,9, 9};

__device__ __forceinline__ void ffma2(unsigned long long& d,
                                      unsigned long long a, unsigned long long b) {
    asm("fma.rn.f32x2 %0, %1, %2, %0;" : "+l"(d) : "l"(a), "l"(b));
}
__device__ __forceinline__ void unpack2(unsigned long long v, float& lo, float& hi) {
    asm("mov.b64 {%0, %1}, %2;" : "=f"(lo), "=f"(hi) : "l"(v));
}

// ---------------------------------------------------------------------------
// Kernel 1: per-vector quantization. 128 CTAs x 512 threads = ONE wave
// (1 CTA/SM, no wave-quantization tail). Norms via bit-path recurrence over
// the 10x10 Gram; dots via packed f32x2; EXACT strict-< argmin (validated).
// ---------------------------------------------------------------------------
__global__ void __launch_bounds__(512, 1)
quant_kernel(const float* __restrict__ inp, const float* __restrict__ w) {
    __shared__ __align__(16) float s_bvp[128][12];   // per channel: 10 slots *(-2), pad 2
    __shared__ float sG[100];                        // gram of scaled rows (= 4 * true gram)
    __shared__ float sC[768];                        // padded codeword norms
    __shared__ float s_loss[8];

    int tid = threadIdx.x, wid = tid >> 5, lane = tid & 31;

    for (int i = tid; i < 1280; i += 512) {
        int c = i & 127, t = i >> 7;
        s_bvp[c][t] = -2.0f * w[c_rl[t] * D + c];
    }
    if (tid < 256) { int c = tid & 127, t = tid >> 7; s_bvp[c][10 + t] = 0.f; }
    if (tid < 8) s_loss[tid] = 0.f;
    __syncthreads();

    // gram over SLOTS (55 pairs across 16 warps)
    for (int p = wid; p < 55; p += 16) {
        int i = c_pi[p], j = c_pj[p];
        float s = 0.f;
        #pragma unroll
        for (int cc = 0; cc < 4; cc++)
            s = fmaf(s_bvp[lane + 32 * cc][i], s_bvp[lane + 32 * cc][j], s);
        #pragma unroll
        for (int o = 16; o; o >>= 1) s += __shfl_xor_sync(0xffffffffu, s, o);
        if (lane == 0) { sG[i * 10 + j] = s; sG[j * 10 + i] = s; }
    }
    __syncthreads();

    // codeword norms via per-thread bit-path recurrence (threads 0..255)
    if (tid < 256) {
        const int padv[8] = {0, 4, 8, 16, 48, 112, 240, 496};
        int u[8];
        #pragma unroll
        for (int l = 1; l <= 8; l++) {
            int bit = (tid >> (8 - l)) & 1;
            u[l - 1] = (l == 1) ? bit : (l + bit);
        }
        float M = 0.f;
        #pragma unroll
        for (int l = 1; l <= 8; l++) {
            float cross = 0.f;
            #pragma unroll
            for (int s = 0; s < l - 1; s++) cross += sG[u[s] * 10 + u[l - 1]];
            M += 2.f * cross + sG[u[l - 1] * 10 + u[l - 1]];
            if ((tid & ((1 << (8 - l)) - 1)) == 0)
                sC[padv[l - 1] + (tid >> (8 - l))] = 0.25f * M;
        }
    }
    __syncthreads();

    int vec = blockIdx.x * 512 + tid;                     // 0..65535
    const float* xp = inp + ((size_t)(vec >> 12) << 19) + (vec & 4095);

    unsigned long long a01 = 0, a34 = 0, a56 = 0, a78 = 0, a910 = 0;
    float xn = 0.f;

    #pragma unroll 8
    for (int c = 0; c < 128; c++) {
        float x = xp[c * 4096];
        unsigned long long xx;
        asm("mov.b64 %0, {%1, %1};" : "=l"(xx) : "f"(x));
        const ulonglong2* bp = reinterpret_cast<const ulonglong2*>(&s_bvp[c][0]);
        ulonglong2 P0 = bp[0];
        ulonglong2 P1 = bp[1];
        unsigned long long P2 = reinterpret_cast<const unsigned long long*>(&s_bvp[c][0])[4];
        ffma2(a01,  xx, P0.x);
        ffma2(a34,  xx, P0.y);
        ffma2(a56,  xx, P1.x);
        ffma2(a78,  xx, P1.y);
        ffma2(a910, xx, P2);
        xn = fmaf(x, x, xn);
    }

    float d0, d1, d3, d4, d5, d6, d7, d8, d9, d10;
    unpack2(a01,  d0, d1);
    unpack2(a34,  d3, d4);
    unpack2(a56,  d5, d6);
    unpack2(a78,  d7, d8);
    unpack2(a910, d9, d10);

    // p[2s+b] = -2 x . v_{s,b}
    float p[16] = {d0, d1, d3, d4, d4, d5, d5, d6, d6, d7, d7, d8, d8, d9, d9, d10};

    float A2[4], A3[8], A4[16], B2[4], B3[8], B4[16];
    #pragma unroll
    for (int j = 0; j < 4;  j++) A2[j] = p[j >> 1] + p[2 + (j & 1)];
    #pragma unroll
    for (int j = 0; j < 8;  j++) A3[j] = A2[j >> 1] + p[4 + (j & 1)];
    #pragma unroll
    for (int j = 0; j < 16; j++) A4[j] = A3[j >> 1] + p[6 + (j & 1)];
    #pragma unroll
    for (int j = 0; j < 4;  j++) B2[j] = p[8 + (j >> 1)] + p[10 + (j & 1)];
    #pragma unroll
    for (int j = 0; j < 8;  j++) B3[j] = B2[j >> 1] + p[12 + (j & 1)];
    #pragma unroll
    for (int j = 0; j < 16; j++) B4[j] = B3[j >> 1] + p[14 + (j & 1)];

    const float INF = __int_as_float(0x7f800000);
    float m[8]; int mi[8];
    #pragma unroll
    for (int l = 0; l < 8; l++) { m[l] = INF; mi[l] = 0; }

    // strict '<' keeps the FIRST minimum (matches jnp.argmin tie-break)
    #pragma unroll
    for (int j = 0; j < 2;   j++) { float s = p[j]            + sC[0   + j]; if (s < m[0]) { m[0] = s; mi[0] = j; } }
    #pragma unroll
    for (int j = 0; j < 4;   j++) { float s = A2[j]           + sC[4   + j]; if (s < m[1]) { m[1] = s; mi[1] = j; } }
    #pragma unroll
    for (int j = 0; j < 8;   j++) { float s = A3[j]           + sC[8   + j]; if (s < m[2]) { m[2] = s; mi[2] = j; } }
    #pragma unroll
    for (int j = 0; j < 16;  j++) { float s = A4[j]           + sC[16  + j]; if (s < m[3]) { m[3] = s; mi[3] = j; } }
    #pragma unroll
    for (int j = 0; j < 32;  j++) { float s = A4[j >> 1] + p[8 + (j & 1)]  + sC[48  + j]; if (s < m[4]) { m[4] = s; mi[4] = j; } }
    #pragma unroll
    for (int j = 0; j < 64;  j++) { float s = A4[j >> 2] + B2[j & 3]       + sC[112 + j]; if (s < m[5]) { m[5] = s; mi[5] = j; } }
    #pragma unroll
    for (int j = 0; j < 128; j++) { float s = A4[j >> 3] + B3[j & 7]       + sC[240 + j]; if (s < m[6]) { m[6] = s; mi[6] = j; } }
    #pragma unroll
    for (int j = 0; j < 256; j++) { float s = A4[j >> 4] + B4[j & 15]      + sC[496 + j]; if (s < m[7]) { m[7] = s; mi[7] = j; } }

    // level-major byte indices (coalesced per level)
    #pragma unroll
    for (int l = 0; l < 8; l++) g_idxb[(l << 16) + vec] = (uint8_t)mi[l];

    #pragma unroll
    for (int l = 0; l < 8; l++) {
        float v = xn + m[l];
        #pragma unroll
        for (int o = 16; o; o >>= 1) v += __shfl_xor_sync(0xffffffffu, v, o);
        if (lane == 0) atomicAdd(&s_loss[l], v);
    }
    __syncthreads();
    if (tid < 8) g_part[blockIdx.x * 8 + tid] = s_loss[tid];
}

// ---------------------------------------------------------------------------
// Kernel 2: output writer (R7 body — fastest measured config). 512 CTAs =
// (8 levels x 16 batches x 4 channel-quarters), heavy levels first, occ 5.
// In-CTA codebook build for its 32 channels, scalar gather, STG.128.
// ---------------------------------------------------------------------------
__global__ void __launch_bounds__(256, 5)
scatter_kernel(const float* __restrict__ w, float* __restrict__ out) {
    __shared__ float    scb[8192];     // 32 channels x sz (<=256)
    __shared__ float    srow[320];     // 10 slots x 32 channels
    __shared__ uint32_t sidx[1024];    // 4096 byte-indices
    __shared__ int      sst[16];

    int bid   = blockIdx.x;
    int level = 7 - (bid >> 6);        // heavy levels first
    int r     = bid & 63;
    int b     = r >> 2;                // 0..15
    int q     = r & 3;                 // channel quarter
    int L     = level + 1;
    int sz    = 2 << level;
    int tid   = threadIdx.x;

    if (tid < 16) sst[tid] = c_st[tid];
    for (int i = tid; i < 320; i += 256)
        srow[i] = w[c_rl[i >> 5] * D + q * 32 + (i & 31)];
    {
        const uint4* src = reinterpret_cast<const uint4*>(
            g_idxb + ((size_t)level << 16) + ((size_t)b << 12));
        reinterpret_cast<uint4*>(sidx)[tid] = src[tid];
    }
    __syncthreads();

    // build codebook slice: scb[cl*sz + j], cl = local channel 0..31
    int n = sz << 5;
    for (int u = tid; u < n; u += 256) {
        int cl = u >> L;
        int j  = u & (sz - 1);
        float v = 0.f;
        #pragma unroll 8
        for (int s = 0; s < L; s++) {
            int bit = (j >> (L - 1 - s)) & 1;
            v += srow[sst[2 * s + bit] * 32 + cl];
        }
        scb[u] = v;
    }
    __syncthreads();

    // loss finalize (one CTA; quant complete by stream order)
    if (bid == 0) {
        int l = tid >> 5, ln = tid & 31;
        float s = 0.f;
        #pragma unroll
        for (int k = 0; k < 4; k++) s += g_part[(ln + 32 * k) * 8 + l];
        #pragma unroll
        for (int o = 16; o; o >>= 1) s += __shfl_xor_sync(0xffffffffu, s, o);
        if (ln == 0)
            out[OUT_TENSOR + l] = (c_coef[l] + 0.4f) * s * (1.0f / 8388608.0f);
    }

    // per-thread indices: quad g covers hw = g*1024 + 4*tid .. +3
    int o[16];
    #pragma unroll
    for (int g = 0; g < 4; g++) {
        uint32_t u = sidx[g * 256 + tid];
        o[4 * g + 0] =  u        & 255;
        o[4 * g + 1] = (u >> 8)  & 255;
        o[4 * g + 2] = (u >> 16) & 255;
        o[4 * g + 3] =  u >> 24;
    }

    // out index = ((level*16 + b)*128 + q*32 + cl) * 4096 + hw
    float* ob = out + ((((size_t)((level << 4) + b) << 7) + ((size_t)(q << 5))) << 12)
                    + (tid << 2);
    const float* row = scb;
    for (int cl = 0; cl < 32; cl++) {
        #pragma unroll
        for (int g = 0; g < 4; g++) {
            float4 v = make_float4(row[o[4 * g + 0]], row[o[4 * g + 1]],
                                   row[o[4 * g + 2]], row[o[4 * g + 3]]);
            *reinterpret_cast<float4*>(ob + g * 1024) = v;
        }
        row += sz;
        ob  += 4096;
    }
}

// ---------------------------------------------------------------------------
extern "C" void kernel_launch(void* const* d_in, const int* in_sizes, int n_in,
                              void* d_out, int out_size) {
    const float* inp = (const float*)d_in[0];   // (16,128,64,64) f32
    const float* w   = (const float*)d_in[1];   // (256,128) f32
    float* out       = (float*)d_out;

    (void)in_sizes; (void)n_in; (void)out_size;

    quant_kernel<<<128, 512>>>(inp, w);
    scatter_kernel<<<512, 256>>>(w, out);
}